// round 6
// baseline (speedup 1.0000x reference)
#include <cuda_runtime.h>
#include <cuda_bf16.h>
#include <cstdint>

#define EN 8192
#define EL 8192
#define DD 256
#define NG 64
#define SLOTS 16

// ---------------- scratch (device globals) ----------------------------------
__device__ __align__(128) __nv_bfloat16 g_efn_bf[EN * DD];
__device__ __align__(128) __nv_bfloat16 g_efl_bf[EL * DD];
__device__ __align__(128) float    g_na[EN];
__device__ __align__(128) float    g_nb[EL];
__device__ __align__(128) unsigned g_rowmin[EN * NG];   // [i][gl]
__device__ __align__(128) unsigned g_colmin[NG * EL];   // [gn][j]
__device__ __align__(128) float    g_outn[NG * NG];

__device__ __forceinline__ unsigned encf(float f) {
    unsigned u = __float_as_uint(f);
    return (u & 0x80000000u) ? ~u : (u | 0x80000000u);
}
__device__ __forceinline__ float decf(unsigned k) {
    unsigned u = (k & 0x80000000u) ? (k & 0x7FFFFFFFu) : ~k;
    return __uint_as_float(u);
}

#define SENTINEL 0xFFFFFFFFu
#define INF_F __int_as_float(0x7f800000)

// ---------------- kernel 0: reset min buffers -------------------------------
__global__ void init_mins_kernel() {
    int i = blockIdx.x * blockDim.x + threadIdx.x;
    if (i < EN * NG) {
        g_rowmin[i] = SENTINEL;
        g_colmin[i] = SENTINEL;
    }
}

// ---------------- kernel 1: ef = (h[e0]+h[e1])*0.5 (bf16) + fp32 norms ------
__global__ void build_ef_kernel(const float* __restrict__ h,
                                const int* __restrict__ edge,
                                int which) {
    __nv_bfloat16* ef = which ? g_efl_bf : g_efn_bf;
    float* nrm        = which ? g_nb     : g_na;
    int e = blockIdx.x;
    int t = threadIdx.x;  // 256 threads == feature dim
    int i0 = edge[e];
    int i1 = edge[EN + e];
    float v = 0.5f * (h[(size_t)i0 * DD + t] + h[(size_t)i1 * DD + t]);
    ef[(size_t)e * DD + t] = __float2bfloat16_rn(v);
    float s = v * v;
    #pragma unroll
    for (int o = 16; o > 0; o >>= 1) s += __shfl_down_sync(0xffffffffu, s, o);
    __shared__ float ws[8];
    if ((t & 31) == 0) ws[t >> 5] = s;
    __syncthreads();
    if (t < 8) {
        float x = ws[t];
        #pragma unroll
        for (int o = 4; o > 0; o >>= 1) x += __shfl_down_sync(0xffu, x, o);
        if (t == 0) nrm[e] = x;
    }
}

// ---------------- PTX helpers -----------------------------------------------
__device__ __forceinline__ void cp16(uint32_t dst, const void* src) {
    asm volatile("cp.async.cg.shared.global [%0], [%1], 16;" :: "r"(dst), "l"(src));
}
__device__ __forceinline__ void cp_commit() {
    asm volatile("cp.async.commit_group;");
}
__device__ __forceinline__ void cp_wait0() {
    asm volatile("cp.async.wait_group 0;");
}
__device__ __forceinline__ void ldmx4(uint32_t* r, uint32_t addr) {
    asm volatile("ldmatrix.sync.aligned.m8n8.x4.shared.b16 {%0,%1,%2,%3}, [%4];"
                 : "=r"(r[0]), "=r"(r[1]), "=r"(r[2]), "=r"(r[3]) : "r"(addr));
}
__device__ __forceinline__ void mma16816(float* d, const uint32_t* a,
                                         uint32_t b0, uint32_t b1) {
    asm volatile("mma.sync.aligned.m16n8k16.row.col.f32.bf16.bf16.f32 "
                 "{%0,%1,%2,%3}, {%4,%5,%6,%7}, {%8,%9}, {%0,%1,%2,%3};"
                 : "+f"(d[0]), "+f"(d[1]), "+f"(d[2]), "+f"(d[3])
                 : "r"(a[0]), "r"(a[1]), "r"(a[2]), "r"(a[3]), "r"(b0), "r"(b1));
}

// ---------------- kernel 2: bf16 MMA GEMM + fused group-min epilogue --------
#define LDA 40
#define STAGE_B (2 * 128 * LDA * 2)
#define HALF_B  (128 * LDA * 2)

__global__ void __launch_bounds__(256, 2)
gemm_bf16_min_kernel(const int* __restrict__ nbatch,
                     const int* __restrict__ lbatch) {
    __shared__ __align__(16) __nv_bfloat16 sAB[2][2][128 * LDA];  // 40960 B
    __shared__ int gnc[128];
    __shared__ int glc[128];

    const int tid   = threadIdx.x;
    const int tileI = blockIdx.y * 128;
    const int tileJ = blockIdx.x * 128;
    const int wid  = tid >> 5;
    const int lane = tid & 31;
    const int wr = wid & 1;
    const int wc = wid >> 1;
    const int wrBase = wr * 64;
    const int wcBase = wc * 32;

    const uint32_t smemBase = (uint32_t)__cvta_generic_to_shared(&sAB[0][0][0]);

    const int aRow = (lane & 7) + ((lane >> 3) & 1) * 8;
    const int aK   = (lane >> 4) * 8;
    const int bRow = (lane & 7) + (lane >> 4) * 8;
    const int bK   = ((lane >> 3) & 1) * 8;

    const int ldRow = tid >> 1;
    const int ldKq  = (tid & 1) * 16;
    const __nv_bfloat16* gA = g_efn_bf + (size_t)(tileI + ldRow) * DD;
    const __nv_bfloat16* gB = g_efl_bf + (size_t)(tileJ + ldRow) * DD;
    const uint32_t dOffA = (uint32_t)(ldRow * LDA + ldKq) * 2;
    const uint32_t dOffB = HALF_B + dOffA;

    if (tid < 128) {
        gnc[tid] = nbatch[tileI + tid];
        glc[tid] = lbatch[tileJ + tid];
    }

    float c[4][4][4];
    #pragma unroll
    for (int mi = 0; mi < 4; mi++)
        #pragma unroll
        for (int ni = 0; ni < 4; ni++)
            #pragma unroll
            for (int q = 0; q < 4; q++) c[mi][ni][q] = 0.f;

    {
        uint32_t st = smemBase;
        cp16(st + dOffA,      gA + ldKq);
        cp16(st + dOffA + 16, gA + ldKq + 8);
        cp16(st + dOffB,      gB + ldKq);
        cp16(st + dOffB + 16, gB + ldKq + 8);
        cp_commit();
    }

    const int NS = DD / 32;  // 8 stages
    for (int s = 0; s < NS; ++s) {
        cp_wait0();
        __syncthreads();
        if (s + 1 < NS) {
            uint32_t st = smemBase + ((s + 1) & 1) * STAGE_B;
            int ko = (s + 1) * 32;
            cp16(st + dOffA,      gA + ko + ldKq);
            cp16(st + dOffA + 16, gA + ko + ldKq + 8);
            cp16(st + dOffB,      gB + ko + ldKq);
            cp16(st + dOffB + 16, gB + ko + ldKq + 8);
            cp_commit();
        }
        uint32_t sA = smemBase + (s & 1) * STAGE_B;
        uint32_t sB = sA + HALF_B;
        #pragma unroll
        for (int kb = 0; kb < 32; kb += 16) {
            uint32_t a[4][4];
            #pragma unroll
            for (int mi = 0; mi < 4; mi++)
                ldmx4(a[mi], sA + (uint32_t)((wrBase + mi * 16 + aRow) * LDA + kb + aK) * 2);
            uint32_t b[2][4];
            #pragma unroll
            for (int nq = 0; nq < 2; nq++)
                ldmx4(b[nq], sB + (uint32_t)((wcBase + nq * 16 + bRow) * LDA + kb + bK) * 2);
            #pragma unroll
            for (int mi = 0; mi < 4; mi++) {
                #pragma unroll
                for (int nq = 0; nq < 2; nq++) {
                    mma16816(c[mi][nq * 2 + 0], a[mi], b[nq][0], b[nq][1]);
                    mma16816(c[mi][nq * 2 + 1], a[mi], b[nq][2], b[nq][3]);
                }
            }
        }
    }
    __syncthreads();

    // -------- epilogue: overlay staging on A/B smem, group-min reduce -------
    unsigned* stag = (unsigned*)&sAB[0][0][0];
    for (int x = tid; x < 128 * SLOTS * 2; x += 256) stag[x] = SENTINEL;
    __syncthreads();
    unsigned (*rm)[SLOTS] = (unsigned(*)[SLOTS])stag;
    unsigned (*cm)[SLOTS] = (unsigned(*)[SLOTS])(stag + 128 * SLOTS);

    const int gl_lo = glc[0], gl_hi = glc[127];
    const int gn_lo = gnc[0], gn_hi = gnc[127];
    const bool fastL = (gl_hi - gl_lo) < SLOTS;
    const bool fastN = (gn_hi - gn_lo) < SLOTS;

    const int g  = lane >> 2;
    const int t2 = (lane & 3) * 2;

    int   lrows[8], grows[8], lcols[8], gcols[8];
    float nav[8], nbv[8];
    #pragma unroll
    for (int m = 0; m < 8; m++) {
        lrows[m] = wrBase + (m >> 1) * 16 + g + (m & 1) * 8;
        grows[m] = gnc[lrows[m]];
        nav[m]   = g_na[tileI + lrows[m]];
    }
    #pragma unroll
    for (int n = 0; n < 8; n++) {
        lcols[n] = wcBase + (n >> 1) * 8 + t2 + (n & 1);
        gcols[n] = glc[lcols[n]];
        nbv[n]   = g_nb[tileJ + lcols[n]];
    }

    // row-side
    #pragma unroll
    for (int m = 0; m < 8; m++) {
        const int mi = m >> 1, hh = m & 1;
        float rbest = INF_F;
        int curgl = -1;
        #pragma unroll
        for (int n = 0; n < 8; n++) {
            const int ni = n >> 1, u = n & 1;
            float rv = fmaf(-2.f, c[mi][ni][hh * 2 + u], nbv[n]);
            int gg = gcols[n];
            if (gg != curgl) {
                if (curgl >= 0) {
                    unsigned k = encf(rbest);
                    if (fastL) atomicMin(&rm[lrows[m]][curgl - gl_lo], k);
                    else       atomicMin(&g_rowmin[(size_t)(tileI + lrows[m]) * NG + curgl], k);
                }
                curgl = gg; rbest = rv;
            } else {
                rbest = fminf(rbest, rv);
            }
        }
        unsigned k = encf(rbest);
        if (fastL) atomicMin(&rm[lrows[m]][curgl - gl_lo], k);
        else       atomicMin(&g_rowmin[(size_t)(tileI + lrows[m]) * NG + curgl], k);
    }

    // col-side
    {
        float cb[8];
        #pragma unroll
        for (int n = 0; n < 8; n++) cb[n] = INF_F;
        int curgn = -1;
        #pragma unroll
        for (int m = 0; m < 8; m++) {
            const int mi = m >> 1, hh = m & 1;
            int gi = grows[m];
            if (gi != curgn) {
                if (curgn >= 0) {
                    #pragma unroll
                    for (int n = 0; n < 8; n++) {
                        unsigned k = encf(cb[n]);
                        if (fastN) atomicMin(&cm[lcols[n]][curgn - gn_lo], k);
                        else       atomicMin(&g_colmin[(size_t)curgn * EL + tileJ + lcols[n]], k);
                        cb[n] = INF_F;
                    }
                }
                curgn = gi;
            }
            #pragma unroll
            for (int n = 0; n < 8; n++) {
                const int ni = n >> 1, u = n & 1;
                cb[n] = fminf(cb[n], fmaf(-2.f, c[mi][ni][hh * 2 + u], nav[m]));
            }
        }
        #pragma unroll
        for (int n = 0; n < 8; n++) {
            unsigned k = encf(cb[n]);
            if (fastN) atomicMin(&cm[lcols[n]][curgn - gn_lo], k);
            else       atomicMin(&g_colmin[(size_t)curgn * EL + tileJ + lcols[n]], k);
        }
    }
    __syncthreads();

    // flush shared staging to global
    if (fastL) {
        for (int x = tid; x < 128 * SLOTS; x += 256) {
            int r = x >> 4, sl = x & (SLOTS - 1);
            unsigned k = rm[r][sl];
            if (k != SENTINEL)
                atomicMin(&g_rowmin[(size_t)(tileI + r) * NG + gl_lo + sl], k);
        }
    }
    if (fastN) {
        for (int x = tid; x < 128 * SLOTS; x += 256) {
            int cc = x >> 4, sl = x & (SLOTS - 1);
            unsigned k = cm[cc][sl];
            if (k != SENTINEL)
                atomicMin(&g_colmin[(size_t)(gn_lo + sl) * EL + tileJ + cc], k);
        }
    }
}

// ---------------- kernel 3: row side -> out_n -------------------------------
__global__ void finalize_row_kernel(const int* __restrict__ nbatch) {
    int gl = blockIdx.x;
    __shared__ float ssum[NG];
    __shared__ int   scnt[NG];
    int t = threadIdx.x;
    if (t < NG) { ssum[t] = 0.f; scnt[t] = 0; }
    __syncthreads();
    for (int i = t; i < EN; i += blockDim.x) {
        unsigned k = g_rowmin[(size_t)i * NG + gl];
        float val = 0.f;
        if (k != SENTINEL) val = -sqrtf(fmaxf(g_na[i] + decf(k), 0.f));
        int gn = nbatch[i];
        int gn0 = __shfl_sync(0xffffffffu, gn, 0);
        if (__all_sync(0xffffffffu, gn == gn0)) {
            #pragma unroll
            for (int o = 16; o > 0; o >>= 1) val += __shfl_down_sync(0xffffffffu, val, o);
            if ((t & 31) == 0) { atomicAdd(&ssum[gn0], val); atomicAdd(&scnt[gn0], 32); }
        } else {
            atomicAdd(&ssum[gn], val); atomicAdd(&scnt[gn], 1);
        }
    }
    __syncthreads();
    if (t < NG) g_outn[(size_t)t * NG + gl] = ssum[t] / (float)max(scnt[t], 1);
}

// ---------------- kernel 4: col side + combine ------------------------------
__global__ void finalize_col_kernel(const int* __restrict__ lbatch,
                                    float* __restrict__ out) {
    int gn = blockIdx.x;
    __shared__ float ssum[NG];
    __shared__ int   scnt[NG];
    int t = threadIdx.x;
    if (t < NG) { ssum[t] = 0.f; scnt[t] = 0; }
    __syncthreads();
    for (int j = t; j < EL; j += blockDim.x) {
        unsigned k = g_colmin[(size_t)gn * EL + j];
        float val = 0.f;
        if (k != SENTINEL) val = -sqrtf(fmaxf(g_nb[j] + decf(k), 0.f));
        int gl = lbatch[j];
        int gl0 = __shfl_sync(0xffffffffu, gl, 0);
        if (__all_sync(0xffffffffu, gl == gl0)) {
            #pragma unroll
            for (int o = 16; o > 0; o >>= 1) val += __shfl_down_sync(0xffffffffu, val, o);
            if ((t & 31) == 0) { atomicAdd(&ssum[gl0], val); atomicAdd(&scnt[gl0], 32); }
        } else {
            atomicAdd(&ssum[gl], val); atomicAdd(&scnt[gl], 1);
        }
    }
    __syncthreads();
    if (t < NG) {
        float out_l = ssum[t] / (float)max(scnt[t], 1);
        out[(size_t)gn * NG + t] = 0.5f * (g_outn[(size_t)gn * NG + t] + out_l);
    }
}

// ---------------- launch ----------------------------------------------------
extern "C" void kernel_launch(void* const* d_in, const int* in_sizes, int n_in,
                              void* d_out, int out_size) {
    const float* h           = (const float*)d_in[0];
    const int*   node_edge   = (const int*)d_in[1];
    const int*   node_batch  = (const int*)d_in[2];
    const int*   label_edge  = (const int*)d_in[3];
    const int*   label_batch = (const int*)d_in[4];
    float* out = (float*)d_out;

    init_mins_kernel<<<(EN * NG + 255) / 256, 256>>>();
    build_ef_kernel<<<EN, 256>>>(h, node_edge, 0);
    build_ef_kernel<<<EL, 256>>>(h, label_edge, 1);
    gemm_bf16_min_kernel<<<dim3(EL / 128, EN / 128), 256>>>(node_batch, label_batch);
    finalize_row_kernel<<<NG, 256>>>(node_batch);
    finalize_col_kernel<<<NG, 256>>>(label_batch, out);
}

// round 7
// speedup vs baseline: 1.0130x; 1.0130x over previous
#include <cuda_runtime.h>
#include <cuda_bf16.h>
#include <cstdint>

#define EN 8192
#define EL 8192
#define DD 256
#define NG 64
#define SLOTS 16

// ---------------- scratch (device globals) ----------------------------------
__device__ __align__(128) __nv_bfloat16 g_efn_bf[EN * DD];
__device__ __align__(128) __nv_bfloat16 g_efl_bf[EL * DD];
__device__ __align__(128) float    g_na[EN];
__device__ __align__(128) float    g_nb[EL];
__device__ __align__(128) unsigned g_rowmin[EN * NG];   // [i][gl]
__device__ __align__(128) unsigned g_colmin[NG * EL];   // [gn][j]
__device__ __align__(128) float    g_outn[NG * NG];

__device__ __forceinline__ unsigned encf(float f) {
    unsigned u = __float_as_uint(f);
    return (u & 0x80000000u) ? ~u : (u | 0x80000000u);
}
__device__ __forceinline__ float decf(unsigned k) {
    unsigned u = (k & 0x80000000u) ? (k & 0x7FFFFFFFu) : ~k;
    return __uint_as_float(u);
}

#define SENTINEL 0xFFFFFFFFu
#define INF_F __int_as_float(0x7f800000)

// ---------------- kernel 0: reset min buffers -------------------------------
__global__ void init_mins_kernel() {
    int i = blockIdx.x * blockDim.x + threadIdx.x;
    if (i < EN * NG) {
        g_rowmin[i] = SENTINEL;
        g_colmin[i] = SENTINEL;
    }
}

// ---------------- kernel 1: ef = (h[e0]+h[e1])*0.5 (bf16) + fp32 norms ------
__global__ void build_ef_kernel(const float* __restrict__ h,
                                const int* __restrict__ edge,
                                int which) {
    __nv_bfloat16* ef = which ? g_efl_bf : g_efn_bf;
    float* nrm        = which ? g_nb     : g_na;
    int e = blockIdx.x;
    int t = threadIdx.x;  // 256 threads == feature dim
    int i0 = edge[e];
    int i1 = edge[EN + e];
    float v = 0.5f * (h[(size_t)i0 * DD + t] + h[(size_t)i1 * DD + t]);
    ef[(size_t)e * DD + t] = __float2bfloat16_rn(v);
    float s = v * v;
    #pragma unroll
    for (int o = 16; o > 0; o >>= 1) s += __shfl_down_sync(0xffffffffu, s, o);
    __shared__ float ws[8];
    if ((t & 31) == 0) ws[t >> 5] = s;
    __syncthreads();
    if (t < 8) {
        float x = ws[t];
        #pragma unroll
        for (int o = 4; o > 0; o >>= 1) x += __shfl_down_sync(0xffu, x, o);
        if (t == 0) nrm[e] = x;
    }
}

// ---------------- PTX helpers -----------------------------------------------
__device__ __forceinline__ void cp16(uint32_t dst, const void* src) {
    asm volatile("cp.async.cg.shared.global [%0], [%1], 16;" :: "r"(dst), "l"(src));
}
__device__ __forceinline__ void cp_commit() {
    asm volatile("cp.async.commit_group;");
}
__device__ __forceinline__ void cp_wait0() {
    asm volatile("cp.async.wait_group 0;");
}
__device__ __forceinline__ void ldmx4(uint32_t* r, uint32_t addr) {
    asm volatile("ldmatrix.sync.aligned.m8n8.x4.shared.b16 {%0,%1,%2,%3}, [%4];"
                 : "=r"(r[0]), "=r"(r[1]), "=r"(r[2]), "=r"(r[3]) : "r"(addr));
}
__device__ __forceinline__ void mma16816(float* d, const uint32_t* a,
                                         uint32_t b0, uint32_t b1) {
    asm volatile("mma.sync.aligned.m16n8k16.row.col.f32.bf16.bf16.f32 "
                 "{%0,%1,%2,%3}, {%4,%5,%6,%7}, {%8,%9}, {%0,%1,%2,%3};"
                 : "+f"(d[0]), "+f"(d[1]), "+f"(d[2]), "+f"(d[3])
                 : "r"(a[0]), "r"(a[1]), "r"(a[2]), "r"(a[3]), "r"(b0), "r"(b1));
}

// ---------------- kernel 2: bf16 MMA GEMM + fused group-min epilogue --------
#define LDA 40
#define STAGE_B (2 * 128 * LDA * 2)
#define HALF_B  (128 * LDA * 2)

__global__ void __launch_bounds__(256, 2)
gemm_bf16_min_kernel(const int* __restrict__ nbatch,
                     const int* __restrict__ lbatch) {
    __shared__ __align__(16) __nv_bfloat16 sAB[2][2][128 * LDA];  // 40960 B
    __shared__ int gnc[128];
    __shared__ int glc[128];

    const int tid   = threadIdx.x;
    const int tileI = blockIdx.y * 128;
    const int tileJ = blockIdx.x * 128;
    const int wid  = tid >> 5;
    const int lane = tid & 31;
    const int wr = wid & 1;
    const int wc = wid >> 1;
    const int wrBase = wr * 64;
    const int wcBase = wc * 32;

    const uint32_t smemBase = (uint32_t)__cvta_generic_to_shared(&sAB[0][0][0]);

    const int aRow = (lane & 7) + ((lane >> 3) & 1) * 8;
    const int aK   = (lane >> 4) * 8;
    const int bRow = (lane & 7) + (lane >> 4) * 8;
    const int bK   = ((lane >> 3) & 1) * 8;

    const int ldRow = tid >> 1;
    const int ldKq  = (tid & 1) * 16;
    const __nv_bfloat16* gA = g_efn_bf + (size_t)(tileI + ldRow) * DD;
    const __nv_bfloat16* gB = g_efl_bf + (size_t)(tileJ + ldRow) * DD;
    const uint32_t dOffA = (uint32_t)(ldRow * LDA + ldKq) * 2;
    const uint32_t dOffB = HALF_B + dOffA;

    if (tid < 128) {
        gnc[tid] = nbatch[tileI + tid];
        glc[tid] = lbatch[tileJ + tid];
    }

    float c[4][4][4];
    #pragma unroll
    for (int mi = 0; mi < 4; mi++)
        #pragma unroll
        for (int ni = 0; ni < 4; ni++)
            #pragma unroll
            for (int q = 0; q < 4; q++) c[mi][ni][q] = 0.f;

    {
        uint32_t st = smemBase;
        cp16(st + dOffA,      gA + ldKq);
        cp16(st + dOffA + 16, gA + ldKq + 8);
        cp16(st + dOffB,      gB + ldKq);
        cp16(st + dOffB + 16, gB + ldKq + 8);
        cp_commit();
    }

    const int NS = DD / 32;  // 8 stages
    for (int s = 0; s < NS; ++s) {
        cp_wait0();
        __syncthreads();
        if (s + 1 < NS) {
            uint32_t st = smemBase + ((s + 1) & 1) * STAGE_B;
            int ko = (s + 1) * 32;
            cp16(st + dOffA,      gA + ko + ldKq);
            cp16(st + dOffA + 16, gA + ko + ldKq + 8);
            cp16(st + dOffB,      gB + ko + ldKq);
            cp16(st + dOffB + 16, gB + ko + ldKq + 8);
            cp_commit();
        }
        uint32_t sA = smemBase + (s & 1) * STAGE_B;
        uint32_t sB = sA + HALF_B;
        #pragma unroll
        for (int kb = 0; kb < 32; kb += 16) {
            uint32_t a[4][4];
            #pragma unroll
            for (int mi = 0; mi < 4; mi++)
                ldmx4(a[mi], sA + (uint32_t)((wrBase + mi * 16 + aRow) * LDA + kb + aK) * 2);
            uint32_t b[2][4];
            #pragma unroll
            for (int nq = 0; nq < 2; nq++)
                ldmx4(b[nq], sB + (uint32_t)((wcBase + nq * 16 + bRow) * LDA + kb + bK) * 2);
            #pragma unroll
            for (int mi = 0; mi < 4; mi++) {
                #pragma unroll
                for (int nq = 0; nq < 2; nq++) {
                    mma16816(c[mi][nq * 2 + 0], a[mi], b[nq][0], b[nq][1]);
                    mma16816(c[mi][nq * 2 + 1], a[mi], b[nq][2], b[nq][3]);
                }
            }
        }
    }
    __syncthreads();

    // -------- epilogue: overlay staging on A/B smem, group-min reduce -------
    unsigned* stag = (unsigned*)&sAB[0][0][0];
    for (int x = tid; x < 128 * SLOTS * 2; x += 256) stag[x] = SENTINEL;
    __syncthreads();
    unsigned (*rm)[SLOTS] = (unsigned(*)[SLOTS])stag;
    unsigned (*cm)[SLOTS] = (unsigned(*)[SLOTS])(stag + 128 * SLOTS);

    const int gl_lo = glc[0], gl_hi = glc[127];
    const int gn_lo = gnc[0], gn_hi = gnc[127];
    const bool fastL = (gl_hi - gl_lo) < SLOTS;
    const bool fastN = (gn_hi - gn_lo) < SLOTS;

    const int g  = lane >> 2;
    const int t2 = (lane & 3) * 2;

    int   lrows[8], grows[8], lcols[8], gcols[8];
    float nav[8], nbv[8];
    #pragma unroll
    for (int m = 0; m < 8; m++) {
        lrows[m] = wrBase + (m >> 1) * 16 + g + (m & 1) * 8;
        grows[m] = gnc[lrows[m]];
        nav[m]   = g_na[tileI + lrows[m]];
    }
    #pragma unroll
    for (int n = 0; n < 8; n++) {
        lcols[n] = wcBase + (n >> 1) * 8 + t2 + (n & 1);
        gcols[n] = glc[lcols[n]];
        nbv[n]   = g_nb[tileJ + lcols[n]];
    }

    // row-side
    #pragma unroll
    for (int m = 0; m < 8; m++) {
        const int mi = m >> 1, hh = m & 1;
        float rbest = INF_F;
        int curgl = -1;
        #pragma unroll
        for (int n = 0; n < 8; n++) {
            const int ni = n >> 1, u = n & 1;
            float rv = fmaf(-2.f, c[mi][ni][hh * 2 + u], nbv[n]);
            int gg = gcols[n];
            if (gg != curgl) {
                if (curgl >= 0) {
                    unsigned k = encf(rbest);
                    if (fastL) atomicMin(&rm[lrows[m]][curgl - gl_lo], k);
                    else       atomicMin(&g_rowmin[(size_t)(tileI + lrows[m]) * NG + curgl], k);
                }
                curgl = gg; rbest = rv;
            } else {
                rbest = fminf(rbest, rv);
            }
        }
        unsigned k = encf(rbest);
        if (fastL) atomicMin(&rm[lrows[m]][curgl - gl_lo], k);
        else       atomicMin(&g_rowmin[(size_t)(tileI + lrows[m]) * NG + curgl], k);
    }

    // col-side
    {
        float cb[8];
        #pragma unroll
        for (int n = 0; n < 8; n++) cb[n] = INF_F;
        int curgn = -1;
        #pragma unroll
        for (int m = 0; m < 8; m++) {
            const int mi = m >> 1, hh = m & 1;
            int gi = grows[m];
            if (gi != curgn) {
                if (curgn >= 0) {
                    #pragma unroll
                    for (int n = 0; n < 8; n++) {
                        unsigned k = encf(cb[n]);
                        if (fastN) atomicMin(&cm[lcols[n]][curgn - gn_lo], k);
                        else       atomicMin(&g_colmin[(size_t)curgn * EL + tileJ + lcols[n]], k);
                        cb[n] = INF_F;
                    }
                }
                curgn = gi;
            }
            #pragma unroll
            for (int n = 0; n < 8; n++) {
                const int ni = n >> 1, u = n & 1;
                cb[n] = fminf(cb[n], fmaf(-2.f, c[mi][ni][hh * 2 + u], nav[m]));
            }
        }
        #pragma unroll
        for (int n = 0; n < 8; n++) {
            unsigned k = encf(cb[n]);
            if (fastN) atomicMin(&cm[lcols[n]][curgn - gn_lo], k);
            else       atomicMin(&g_colmin[(size_t)curgn * EL + tileJ + lcols[n]], k);
        }
    }
    __syncthreads();

    // flush shared staging to global
    if (fastL) {
        for (int x = tid; x < 128 * SLOTS; x += 256) {
            int r = x >> 4, sl = x & (SLOTS - 1);
            unsigned k = rm[r][sl];
            if (k != SENTINEL)
                atomicMin(&g_rowmin[(size_t)(tileI + r) * NG + gl_lo + sl], k);
        }
    }
    if (fastN) {
        for (int x = tid; x < 128 * SLOTS; x += 256) {
            int cc = x >> 4, sl = x & (SLOTS - 1);
            unsigned k = cm[cc][sl];
            if (k != SENTINEL)
                atomicMin(&g_colmin[(size_t)(gn_lo + sl) * EL + tileJ + cc], k);
        }
    }
}

// ---------------- kernel 3: row side -> out_n -------------------------------
__global__ void finalize_row_kernel(const int* __restrict__ nbatch) {
    int gl = blockIdx.x;
    __shared__ float ssum[NG];
    __shared__ int   scnt[NG];
    int t = threadIdx.x;
    if (t < NG) { ssum[t] = 0.f; scnt[t] = 0; }
    __syncthreads();
    for (int i = t; i < EN; i += blockDim.x) {
        unsigned k = g_rowmin[(size_t)i * NG + gl];
        float val = 0.f;
        if (k != SENTINEL) val = -sqrtf(fmaxf(g_na[i] + decf(k), 0.f));
        int gn = nbatch[i];
        int gn0 = __shfl_sync(0xffffffffu, gn, 0);
        if (__all_sync(0xffffffffu, gn == gn0)) {
            #pragma unroll
            for (int o = 16; o > 0; o >>= 1) val += __shfl_down_sync(0xffffffffu, val, o);
            if ((t & 31) == 0) { atomicAdd(&ssum[gn0], val); atomicAdd(&scnt[gn0], 32); }
        } else {
            atomicAdd(&ssum[gn], val); atomicAdd(&scnt[gn], 1);
        }
    }
    __syncthreads();
    if (t < NG) g_outn[(size_t)t * NG + gl] = ssum[t] / (float)max(scnt[t], 1);
}

// ---------------- kernel 4: col side + combine ------------------------------
__global__ void finalize_col_kernel(const int* __restrict__ lbatch,
                                    float* __restrict__ out) {
    int gn = blockIdx.x;
    __shared__ float ssum[NG];
    __shared__ int   scnt[NG];
    int t = threadIdx.x;
    if (t < NG) { ssum[t] = 0.f; scnt[t] = 0; }
    __syncthreads();
    for (int j = t; j < EL; j += blockDim.x) {
        unsigned k = g_colmin[(size_t)gn * EL + j];
        float val = 0.f;
        if (k != SENTINEL) val = -sqrtf(fmaxf(g_nb[j] + decf(k), 0.f));
        int gl = lbatch[j];
        int gl0 = __shfl_sync(0xffffffffu, gl, 0);
        if (__all_sync(0xffffffffu, gl == gl0)) {
            #pragma unroll
            for (int o = 16; o > 0; o >>= 1) val += __shfl_down_sync(0xffffffffu, val, o);
            if ((t & 31) == 0) { atomicAdd(&ssum[gl0], val); atomicAdd(&scnt[gl0], 32); }
        } else {
            atomicAdd(&ssum[gl], val); atomicAdd(&scnt[gl], 1);
        }
    }
    __syncthreads();
    if (t < NG) {
        float out_l = ssum[t] / (float)max(scnt[t], 1);
        out[(size_t)gn * NG + t] = 0.5f * (g_outn[(size_t)gn * NG + t] + out_l);
    }
}

// ---------------- launch ----------------------------------------------------
extern "C" void kernel_launch(void* const* d_in, const int* in_sizes, int n_in,
                              void* d_out, int out_size) {
    const float* h           = (const float*)d_in[0];
    const int*   node_edge   = (const int*)d_in[1];
    const int*   node_batch  = (const int*)d_in[2];
    const int*   label_edge  = (const int*)d_in[3];
    const int*   label_batch = (const int*)d_in[4];
    float* out = (float*)d_out;

    init_mins_kernel<<<(EN * NG + 255) / 256, 256>>>();
    build_ef_kernel<<<EN, 256>>>(h, node_edge, 0);
    build_ef_kernel<<<EL, 256>>>(h, label_edge, 1);
    gemm_bf16_min_kernel<<<dim3(EL / 128, EN / 128), 256>>>(node_batch, label_batch);
    finalize_row_kernel<<<NG, 256>>>(node_batch);
    finalize_col_kernel<<<NG, 256>>>(label_batch, out);
}

// round 10
// speedup vs baseline: 1.2835x; 1.2671x over previous
#include <cuda_runtime.h>
#include <cuda_bf16.h>
#include <cstdint>

#define EN 8192
#define EL 8192
#define DD 256
#define NG 64
#define SLOTS 16

// ---------------- scratch (device globals) ----------------------------------
__device__ __align__(128) __nv_bfloat16 g_efn_bf[EN * DD];
__device__ __align__(128) __nv_bfloat16 g_efl_bf[EL * DD];
__device__ __align__(128) float    g_na[EN];
__device__ __align__(128) float    g_nb[EL];
__device__ __align__(128) unsigned g_rowmin[EN * NG];   // [i][gl]   (R7 layout)
__device__ __align__(128) unsigned g_colmin[NG * EL];   // [gn][j]
__device__ __align__(128) float    g_sumn[NG * NG];     // [gn][gl] row-side sums
__device__ __align__(128) float    g_suml[NG * NG];     // [gn][gl] col-side sums
__device__ __align__(128) int      g_cntn[NG];
__device__ __align__(128) int      g_cntl[NG];

__device__ __forceinline__ unsigned encf(float f) {
    unsigned u = __float_as_uint(f);
    return (u & 0x80000000u) ? ~u : (u | 0x80000000u);
}
__device__ __forceinline__ float decf(unsigned k) {
    unsigned u = (k & 0x80000000u) ? (k & 0x7FFFFFFFu) : ~k;
    return __uint_as_float(u);
}

#define SENTINEL 0xFFFFFFFFu
#define INF_F __int_as_float(0x7f800000)

// ---------------- kernel 0: reset min buffers + sums ------------------------
__global__ void init_mins_kernel() {
    int i = blockIdx.x * blockDim.x + threadIdx.x;
    if (i < EN * NG) {
        g_rowmin[i] = SENTINEL;
        g_colmin[i] = SENTINEL;
    }
    if (i < NG * NG) { g_sumn[i] = 0.f; g_suml[i] = 0.f; }
    if (i < NG)      { g_cntn[i] = 0;   g_cntl[i] = 0; }
}

// ---------------- kernel 1: ef = (h[e0]+h[e1])*0.5 (bf16) + fp32 norms ------
__global__ void build_ef_kernel(const float* __restrict__ h,
                                const int* __restrict__ edge,
                                int which) {
    __nv_bfloat16* ef = which ? g_efl_bf : g_efn_bf;
    float* nrm        = which ? g_nb     : g_na;
    int e = blockIdx.x;
    int t = threadIdx.x;
    int i0 = edge[e];
    int i1 = edge[EN + e];
    float v = 0.5f * (h[(size_t)i0 * DD + t] + h[(size_t)i1 * DD + t]);
    ef[(size_t)e * DD + t] = __float2bfloat16_rn(v);
    float s = v * v;
    #pragma unroll
    for (int o = 16; o > 0; o >>= 1) s += __shfl_down_sync(0xffffffffu, s, o);
    __shared__ float ws[8];
    if ((t & 31) == 0) ws[t >> 5] = s;
    __syncthreads();
    if (t < 8) {
        float x = ws[t];
        #pragma unroll
        for (int o = 4; o > 0; o >>= 1) x += __shfl_down_sync(0xffu, x, o);
        if (t == 0) nrm[e] = x;
    }
}

// ---------------- PTX helpers -----------------------------------------------
__device__ __forceinline__ void cp16(uint32_t dst, const void* src) {
    asm volatile("cp.async.cg.shared.global [%0], [%1], 16;" :: "r"(dst), "l"(src));
}
__device__ __forceinline__ void cp_commit() {
    asm volatile("cp.async.commit_group;");
}
__device__ __forceinline__ void cp_wait0() {
    asm volatile("cp.async.wait_group 0;");
}
__device__ __forceinline__ void ldmx4(uint32_t* r, uint32_t addr) {
    asm volatile("ldmatrix.sync.aligned.m8n8.x4.shared.b16 {%0,%1,%2,%3}, [%4];"
                 : "=r"(r[0]), "=r"(r[1]), "=r"(r[2]), "=r"(r[3]) : "r"(addr));
}
__device__ __forceinline__ void mma16816(float* d, const uint32_t* a,
                                         uint32_t b0, uint32_t b1) {
    asm volatile("mma.sync.aligned.m16n8k16.row.col.f32.bf16.bf16.f32 "
                 "{%0,%1,%2,%3}, {%4,%5,%6,%7}, {%8,%9}, {%0,%1,%2,%3};"
                 : "+f"(d[0]), "+f"(d[1]), "+f"(d[2]), "+f"(d[3])
                 : "r"(a[0]), "r"(a[1]), "r"(a[2]), "r"(a[3]), "r"(b0), "r"(b1));
}

// ---------------- kernel 2: bf16 MMA GEMM + fused group-min epilogue --------
// FROZEN: byte-identical to the R7 passing version.
#define LDA 40
#define STAGE_B (2 * 128 * LDA * 2)
#define HALF_B  (128 * LDA * 2)

__global__ void __launch_bounds__(256, 2)
gemm_bf16_min_kernel(const int* __restrict__ nbatch,
                     const int* __restrict__ lbatch) {
    __shared__ __align__(16) __nv_bfloat16 sAB[2][2][128 * LDA];
    __shared__ int gnc[128];
    __shared__ int glc[128];

    const int tid   = threadIdx.x;
    const int tileI = blockIdx.y * 128;
    const int tileJ = blockIdx.x * 128;
    const int wid  = tid >> 5;
    const int lane = tid & 31;
    const int wr = wid & 1;
    const int wc = wid >> 1;
    const int wrBase = wr * 64;
    const int wcBase = wc * 32;

    const uint32_t smemBase = (uint32_t)__cvta_generic_to_shared(&sAB[0][0][0]);

    const int aRow = (lane & 7) + ((lane >> 3) & 1) * 8;
    const int aK   = (lane >> 4) * 8;
    const int bRow = (lane & 7) + (lane >> 4) * 8;
    const int bK   = ((lane >> 3) & 1) * 8;

    const int ldRow = tid >> 1;
    const int ldKq  = (tid & 1) * 16;
    const __nv_bfloat16* gA = g_efn_bf + (size_t)(tileI + ldRow) * DD;
    const __nv_bfloat16* gB = g_efl_bf + (size_t)(tileJ + ldRow) * DD;
    const uint32_t dOffA = (uint32_t)(ldRow * LDA + ldKq) * 2;
    const uint32_t dOffB = HALF_B + dOffA;

    if (tid < 128) {
        gnc[tid] = nbatch[tileI + tid];
        glc[tid] = lbatch[tileJ + tid];
    }

    float c[4][4][4];
    #pragma unroll
    for (int mi = 0; mi < 4; mi++)
        #pragma unroll
        for (int ni = 0; ni < 4; ni++)
            #pragma unroll
            for (int q = 0; q < 4; q++) c[mi][ni][q] = 0.f;

    {
        uint32_t st = smemBase;
        cp16(st + dOffA,      gA + ldKq);
        cp16(st + dOffA + 16, gA + ldKq + 8);
        cp16(st + dOffB,      gB + ldKq);
        cp16(st + dOffB + 16, gB + ldKq + 8);
        cp_commit();
    }

    const int NS = DD / 32;
    for (int s = 0; s < NS; ++s) {
        cp_wait0();
        __syncthreads();
        if (s + 1 < NS) {
            uint32_t st = smemBase + ((s + 1) & 1) * STAGE_B;
            int ko = (s + 1) * 32;
            cp16(st + dOffA,      gA + ko + ldKq);
            cp16(st + dOffA + 16, gA + ko + ldKq + 8);
            cp16(st + dOffB,      gB + ko + ldKq);
            cp16(st + dOffB + 16, gB + ko + ldKq + 8);
            cp_commit();
        }
        uint32_t sA = smemBase + (s & 1) * STAGE_B;
        uint32_t sB = sA + HALF_B;
        #pragma unroll
        for (int kb = 0; kb < 32; kb += 16) {
            uint32_t a[4][4];
            #pragma unroll
            for (int mi = 0; mi < 4; mi++)
                ldmx4(a[mi], sA + (uint32_t)((wrBase + mi * 16 + aRow) * LDA + kb + aK) * 2);
            uint32_t b[2][4];
            #pragma unroll
            for (int nq = 0; nq < 2; nq++)
                ldmx4(b[nq], sB + (uint32_t)((wcBase + nq * 16 + bRow) * LDA + kb + bK) * 2);
            #pragma unroll
            for (int mi = 0; mi < 4; mi++) {
                #pragma unroll
                for (int nq = 0; nq < 2; nq++) {
                    mma16816(c[mi][nq * 2 + 0], a[mi], b[nq][0], b[nq][1]);
                    mma16816(c[mi][nq * 2 + 1], a[mi], b[nq][2], b[nq][3]);
                }
            }
        }
    }
    __syncthreads();

    unsigned* stag = (unsigned*)&sAB[0][0][0];
    for (int x = tid; x < 128 * SLOTS * 2; x += 256) stag[x] = SENTINEL;
    __syncthreads();
    unsigned (*rm)[SLOTS] = (unsigned(*)[SLOTS])stag;
    unsigned (*cm)[SLOTS] = (unsigned(*)[SLOTS])(stag + 128 * SLOTS);

    const int gl_lo = glc[0], gl_hi = glc[127];
    const int gn_lo = gnc[0], gn_hi = gnc[127];
    const bool fastL = (gl_hi - gl_lo) < SLOTS;
    const bool fastN = (gn_hi - gn_lo) < SLOTS;

    const int g  = lane >> 2;
    const int t2 = (lane & 3) * 2;

    int   lrows[8], grows[8], lcols[8], gcols[8];
    float nav[8], nbv[8];
    #pragma unroll
    for (int m = 0; m < 8; m++) {
        lrows[m] = wrBase + (m >> 1) * 16 + g + (m & 1) * 8;
        grows[m] = gnc[lrows[m]];
        nav[m]   = g_na[tileI + lrows[m]];
    }
    #pragma unroll
    for (int n = 0; n < 8; n++) {
        lcols[n] = wcBase + (n >> 1) * 8 + t2 + (n & 1);
        gcols[n] = glc[lcols[n]];
        nbv[n]   = g_nb[tileJ + lcols[n]];
    }

    #pragma unroll
    for (int m = 0; m < 8; m++) {
        const int mi = m >> 1, hh = m & 1;
        float rbest = INF_F;
        int curgl = -1;
        #pragma unroll
        for (int n = 0; n < 8; n++) {
            const int ni = n >> 1, u = n & 1;
            float rv = fmaf(-2.f, c[mi][ni][hh * 2 + u], nbv[n]);
            int gg = gcols[n];
            if (gg != curgl) {
                if (curgl >= 0) {
                    unsigned k = encf(rbest);
                    if (fastL) atomicMin(&rm[lrows[m]][curgl - gl_lo], k);
                    else       atomicMin(&g_rowmin[(size_t)(tileI + lrows[m]) * NG + curgl], k);
                }
                curgl = gg; rbest = rv;
            } else {
                rbest = fminf(rbest, rv);
            }
        }
        unsigned k = encf(rbest);
        if (fastL) atomicMin(&rm[lrows[m]][curgl - gl_lo], k);
        else       atomicMin(&g_rowmin[(size_t)(tileI + lrows[m]) * NG + curgl], k);
    }

    {
        float cb[8];
        #pragma unroll
        for (int n = 0; n < 8; n++) cb[n] = INF_F;
        int curgn = -1;
        #pragma unroll
        for (int m = 0; m < 8; m++) {
            const int mi = m >> 1, hh = m & 1;
            int gi = grows[m];
            if (gi != curgn) {
                if (curgn >= 0) {
                    #pragma unroll
                    for (int n = 0; n < 8; n++) {
                        unsigned k = encf(cb[n]);
                        if (fastN) atomicMin(&cm[lcols[n]][curgn - gn_lo], k);
                        else       atomicMin(&g_colmin[(size_t)curgn * EL + tileJ + lcols[n]], k);
                        cb[n] = INF_F;
                    }
                }
                curgn = gi;
            }
            #pragma unroll
            for (int n = 0; n < 8; n++) {
                const int ni = n >> 1, u = n & 1;
                cb[n] = fminf(cb[n], fmaf(-2.f, c[mi][ni][hh * 2 + u], nav[m]));
            }
        }
        #pragma unroll
        for (int n = 0; n < 8; n++) {
            unsigned k = encf(cb[n]);
            if (fastN) atomicMin(&cm[lcols[n]][curgn - gn_lo], k);
            else       atomicMin(&g_colmin[(size_t)curgn * EL + tileJ + lcols[n]], k);
        }
    }
    __syncthreads();

    if (fastL) {
        for (int x = tid; x < 128 * SLOTS; x += 256) {
            int r = x >> 4, sl = x & (SLOTS - 1);
            unsigned k = rm[r][sl];
            if (k != SENTINEL)
                atomicMin(&g_rowmin[(size_t)(tileI + r) * NG + gl_lo + sl], k);
        }
    }
    if (fastN) {
        for (int x = tid; x < 128 * SLOTS; x += 256) {
            int cc = x >> 4, sl = x & (SLOTS - 1);
            unsigned k = cm[cc][sl];
            if (k != SENTINEL)
                atomicMin(&g_colmin[(size_t)(gn_lo + sl) * EL + tileJ + cc], k);
        }
    }
}

// ---------------- kernel 2b: group-size histogram ----------------------------
__global__ void hist_kernel(const int* __restrict__ nbatch,
                            const int* __restrict__ lbatch) {
    int idx = blockIdx.x * blockDim.x + threadIdx.x;
    if (idx < EN) atomicAdd(&g_cntn[nbatch[idx]], 1);
    else if (idx < EN + EL) atomicAdd(&g_cntl[lbatch[idx - EN]], 1);
}

// ---------------- kernel 3: row-side sums: grid (NG, 16) --------------------
__global__ void row_sum_kernel(const int* __restrict__ nbatch) {
    int gl = blockIdx.x;
    int base = blockIdx.y * 512;
    int t = threadIdx.x;
    #pragma unroll
    for (int it = 0; it < 2; ++it) {
        int i = base + it * 256 + t;
        unsigned k = g_rowmin[(size_t)i * NG + gl];
        float val = 0.f;
        if (k != SENTINEL) val = -sqrtf(fmaxf(g_na[i] + decf(k), 0.f));
        int gn = nbatch[i];
        int gn0 = __shfl_sync(0xffffffffu, gn, 0);
        if (__all_sync(0xffffffffu, gn == gn0)) {
            #pragma unroll
            for (int o = 16; o > 0; o >>= 1) val += __shfl_down_sync(0xffffffffu, val, o);
            if ((t & 31) == 0) atomicAdd(&g_sumn[gn0 * NG + gl], val);
        } else {
            atomicAdd(&g_sumn[gn * NG + gl], val);
        }
    }
}

// ---------------- kernel 4: col-side sums: grid (NG, 16) --------------------
__global__ void col_sum_kernel(const int* __restrict__ lbatch) {
    int gn = blockIdx.x;
    int base = blockIdx.y * 512;
    int t = threadIdx.x;
    #pragma unroll
    for (int it = 0; it < 2; ++it) {
        int j = base + it * 256 + t;
        unsigned k = g_colmin[(size_t)gn * EL + j];
        float val = 0.f;
        if (k != SENTINEL) val = -sqrtf(fmaxf(g_nb[j] + decf(k), 0.f));
        int gl = lbatch[j];
        int gl0 = __shfl_sync(0xffffffffu, gl, 0);
        if (__all_sync(0xffffffffu, gl == gl0)) {
            #pragma unroll
            for (int o = 16; o > 0; o >>= 1) val += __shfl_down_sync(0xffffffffu, val, o);
            if ((t & 31) == 0) atomicAdd(&g_suml[gn * NG + gl0], val);
        } else {
            atomicAdd(&g_suml[gn * NG + gl], val);
        }
    }
}

// ---------------- kernel 5: combine -----------------------------------------
__global__ void combine_kernel(float* __restrict__ out) {
    int idx = blockIdx.x * blockDim.x + threadIdx.x;
    if (idx < NG * NG) {
        int gn = idx >> 6, gl = idx & (NG - 1);
        float on = g_sumn[idx] / (float)max(g_cntn[gn], 1);
        float ol = g_suml[idx] / (float)max(g_cntl[gl], 1);
        out[idx] = 0.5f * (on + ol);
    }
}

// ---------------- launch ----------------------------------------------------
extern "C" void kernel_launch(void* const* d_in, const int* in_sizes, int n_in,
                              void* d_out, int out_size) {
    const float* h           = (const float*)d_in[0];
    const int*   node_edge   = (const int*)d_in[1];
    const int*   node_batch  = (const int*)d_in[2];
    const int*   label_edge  = (const int*)d_in[3];
    const int*   label_batch = (const int*)d_in[4];
    float* out = (float*)d_out;

    init_mins_kernel<<<(EN * NG + 255) / 256, 256>>>();
    build_ef_kernel<<<EN, 256>>>(h, node_edge, 0);
    build_ef_kernel<<<EL, 256>>>(h, label_edge, 1);
    gemm_bf16_min_kernel<<<dim3(EL / 128, EN / 128), 256>>>(node_batch, label_batch);
    hist_kernel<<<(EN + EL + 255) / 256, 256>>>(node_batch, label_batch);
    row_sum_kernel<<<dim3(NG, 16), 256>>>(node_batch);
    col_sum_kernel<<<dim3(NG, 16), 256>>>(label_batch);
    combine_kernel<<<(NG * NG + 255) / 256, 256>>>(out);
}